// round 6
// baseline (speedup 1.0000x reference)
#include <cuda_runtime.h>
#include <cuda_fp16.h>
#include <cstdint>

// ---------------------------------------------------------------------------
// NodeBernNet fixed shapes: N=100000, E=1600000, C_IN=128, C=64, F=2, K+1=4.
// R6: fp16 gather operands (fp32 accumulate); self-zeroing CSR (atomicSub
// scatter, no memset/no g_cur); split-GEMM overlapped with count & scatter.
// ---------------------------------------------------------------------------

#define NMAX 100000
#define EMAX 1600000
#define CDIM 64

__device__ __align__(256) float  g_h   [NMAX * CDIM];
__device__ __align__(256) float  g_T1  [NMAX * CDIM];
__device__ __align__(256) float  g_T2  [NMAX * CDIM];
__device__ __align__(256) __half g_h16 [NMAX * CDIM];
__device__ __align__(256) __half g_T116[NMAX * CDIM];
__device__ __align__(256) __half g_T216[NMAX * CDIM];
// CSR scratch
__device__ int   g_cnt [NMAX];      // count adds, scatter subtracts -> 0
__device__ int   g_incl[NMAX];
__device__ int   g_bsum[128];
__device__ int   g_off [NMAX + 1];
__device__ __align__(16) int2 g_csr[EMAX];   // {src, val bits}

__device__ float g_coef[8];   // thetas @ BCOEF, [F=2][K+1=4]
__device__ int   g_is64;

// ---------------------------------------------------------------------------
__global__ void prep_kernel(const void* __restrict__ esrc,
                            const float* __restrict__ thetas)
{
    if (threadIdx.x == 0) {
        const int* w = (const int*)esrc;
        g_is64 = (w[1] == 0 && w[3] == 0 && w[5] == 0 && w[7] == 0) ? 1 : 0;
        const float B[4][4] = {
            {1.f, -3.f,  3.f, -1.f},
            {0.f,  3.f, -6.f,  3.f},
            {0.f,  0.f,  3.f, -3.f},
            {0.f,  0.f,  0.f,  1.f}};
        for (int f = 0; f < 2; f++)
            for (int k = 0; k < 4; k++) {
                float s = 0.f;
                for (int j = 0; j < 4; j++) s += thetas[f * 4 + j] * B[j][k];
                g_coef[f * 4 + k] = s;
            }
    }
}

// ---------------------------------------------------------------------------
// fp16 helpers
// ---------------------------------------------------------------------------
__device__ __forceinline__ float4 h4_to_f4(uint2 q)
{
    __half2 l = *reinterpret_cast<__half2*>(&q.x);
    __half2 h = *reinterpret_cast<__half2*>(&q.y);
    float2 a = __half22float2(l);
    float2 b = __half22float2(h);
    return make_float4(a.x, a.y, b.x, b.y);
}

__device__ __forceinline__ void store_h4(__half* p, float4 v)
{
    __half2 l = __floats2half2_rn(v.x, v.y);
    __half2 h = __floats2half2_rn(v.z, v.w);
    uint2 q;
    q.x = *reinterpret_cast<unsigned*>(&l);
    q.y = *reinterpret_cast<unsigned*>(&h);
    *reinterpret_cast<uint2*>(p) = q;
}

// ---------------------------------------------------------------------------
// Shared GEMM body: h = relu(x @ W_in + b_in), 128-row tile at m0.
// Writes fp32 and fp16 copies of h.
// ---------------------------------------------------------------------------
__device__ void gemm_body(const float* __restrict__ A,
                          const float* __restrict__ W,
                          const float* __restrict__ bias,
                          float* __restrict__ C, __half* __restrict__ C16,
                          int M, int m0)
{
    __shared__ float As[16][132];
    __shared__ float Bs[16][68];

    const int tid = threadIdx.x;
    const int tx = tid & 15;
    const int ty = tid >> 4;

    float acc[8][4] = {};

    for (int k0 = 0; k0 < 128; k0 += 16) {
        #pragma unroll
        for (int r = 0; r < 2; r++) {
            int i = tid + r * 256;
            int row = i >> 2, kq = i & 3;
            int gm = m0 + row;
            float4 v = make_float4(0.f, 0.f, 0.f, 0.f);
            if (gm < M) v = *(const float4*)(A + (size_t)gm * 128 + k0 + kq * 4);
            As[kq * 4 + 0][row] = v.x;
            As[kq * 4 + 1][row] = v.y;
            As[kq * 4 + 2][row] = v.z;
            As[kq * 4 + 3][row] = v.w;
        }
        {
            int k = tid >> 4, nn = (tid & 15) * 4;
            float4 v = *(const float4*)(W + (size_t)(k0 + k) * 64 + nn);
            Bs[k][nn + 0] = v.x; Bs[k][nn + 1] = v.y;
            Bs[k][nn + 2] = v.z; Bs[k][nn + 3] = v.w;
        }
        __syncthreads();
        #pragma unroll
        for (int kk = 0; kk < 16; kk++) {
            float4 a0 = *(const float4*)&As[kk][ty * 8];
            float4 a1 = *(const float4*)&As[kk][ty * 8 + 4];
            float4 b  = *(const float4*)&Bs[kk][tx * 4];
            float am[8] = {a0.x, a0.y, a0.z, a0.w, a1.x, a1.y, a1.z, a1.w};
            float bn[4] = {b.x, b.y, b.z, b.w};
            #pragma unroll
            for (int i = 0; i < 8; i++)
                #pragma unroll
                for (int j = 0; j < 4; j++)
                    acc[i][j] += am[i] * bn[j];
        }
        __syncthreads();
    }

    int nn = tx * 4;
    float4 bv = *(const float4*)(bias + nn);
    #pragma unroll
    for (int i = 0; i < 8; i++) {
        int gm = m0 + ty * 8 + i;
        if (gm >= M) continue;
        float4 o;
        o.x = fmaxf(acc[i][0] + bv.x, 0.f);
        o.y = fmaxf(acc[i][1] + bv.y, 0.f);
        o.z = fmaxf(acc[i][2] + bv.z, 0.f);
        o.w = fmaxf(acc[i][3] + bv.w, 0.f);
        *(float4*)(C + (size_t)gm * 64 + nn) = o;
        store_h4(C16 + (size_t)gm * 64 + nn, o);
    }
}

// ---------------------------------------------------------------------------
// Fat kernel 1: blocks [0,GA) gemm rows [0, GA*128); blocks [GA,..) count.
// ---------------------------------------------------------------------------
__global__ void fat1(const float* __restrict__ A,
                     const float* __restrict__ W,
                     const float* __restrict__ bias,
                     float* __restrict__ C, __half* __restrict__ C16, int M,
                     const void* __restrict__ edst, int E, int GA)
{
    if ((int)blockIdx.x >= GA) {
        int e = (blockIdx.x - GA) * blockDim.x + threadIdx.x;
        if (e < E) {
            int dst = g_is64 ? (int)((const long long*)edst)[e]
                             : ((const int*)edst)[e];
            atomicAdd(&g_cnt[dst], 1);
        }
        return;
    }
    gemm_body(A, W, bias, C, C16, M, blockIdx.x * 128);
}

// ---------------------------------------------------------------------------
// Scan (two kernels)
// ---------------------------------------------------------------------------
__global__ void scan1_kernel(int n)
{
    __shared__ int sh[1024];
    int t = threadIdx.x, i = blockIdx.x * 1024 + t;
    int v = (i < n) ? g_cnt[i] : 0;
    sh[t] = v;
    __syncthreads();
    #pragma unroll
    for (int off = 1; off < 1024; off <<= 1) {
        int x = (t >= off) ? sh[t - off] : 0;
        __syncthreads();
        sh[t] += x;
        __syncthreads();
    }
    if (i < n) g_incl[i] = sh[t];
    if (t == 1023) g_bsum[blockIdx.x] = sh[t];
}

__global__ void scan2_kernel(int nb)
{
    __shared__ int sh[128];
    int t = threadIdx.x;
    int v = (t < nb) ? g_bsum[t] : 0;
    sh[t] = v;
    __syncthreads();
    #pragma unroll
    for (int off = 1; off < 128; off <<= 1) {
        int x = (t >= off) ? sh[t - off] : 0;
        __syncthreads();
        sh[t] += x;
        __syncthreads();
    }
    g_bsum[t] = sh[t] - v;   // exclusive block offsets
}

// ---------------------------------------------------------------------------
// Fat kernel 2: blocks [0,GB) gemm rows from GA*128; [GB,GB+OB) write g_off;
// [GB+OB,..) scatter via atomicSub (consumes g_cnt back to zero).
// ---------------------------------------------------------------------------
__global__ void fat2(const float* __restrict__ A,
                     const float* __restrict__ W,
                     const float* __restrict__ bias,
                     float* __restrict__ C, __half* __restrict__ C16, int M,
                     const void* __restrict__ esrc,
                     const void* __restrict__ edst,
                     const float* __restrict__ ev,
                     int E, int n, int GA, int GB, int OB)
{
    if ((int)blockIdx.x >= GB) {
        int bi = blockIdx.x - GB;
        if (bi < OB) {           // off-writer
            int i = bi * 256 + threadIdx.x;
            if (i < n) g_off[i + 1] = g_incl[i] + g_bsum[i >> 10];
            if (bi == 0 && threadIdx.x == 0) g_off[0] = 0;
            return;
        }
        int e = (bi - OB) * 256 + threadIdx.x;
        if (e < E) {
            int src, dst;
            if (g_is64) {
                src = (int)((const long long*)esrc)[e];
                dst = (int)((const long long*)edst)[e];
            } else {
                src = ((const int*)esrc)[e];
                dst = ((const int*)edst)[e];
            }
            int tot = g_incl[dst] + g_bsum[dst >> 10];
            int old = atomicSub(&g_cnt[dst], 1);   // old in [1, cnt]
            g_csr[tot - old] = make_int2(src, __float_as_int(ev[e]));
        }
        return;
    }
    gemm_body(A, W, bias, C, C16, M, (GA + blockIdx.x) * 128);
}

// ---------------------------------------------------------------------------
// CSR row gather-accumulate over fp16 rows, fp32 accumulation, unroll-4.
// ---------------------------------------------------------------------------
__device__ __forceinline__ float4 row_acc_h16(const __half* __restrict__ hin,
                                              int s, int e, int lane16)
{
    float4 acc = make_float4(0.f, 0.f, 0.f, 0.f);
    int i = s;
    for (; i + 3 < e; i += 4) {
        int2 p0 = __ldg(&g_csr[i]);
        int2 p1 = __ldg(&g_csr[i + 1]);
        int2 p2 = __ldg(&g_csr[i + 2]);
        int2 p3 = __ldg(&g_csr[i + 3]);
        uint2 q0 = *((const uint2*)(hin + (size_t)p0.x * CDIM) + lane16);
        uint2 q1 = *((const uint2*)(hin + (size_t)p1.x * CDIM) + lane16);
        uint2 q2 = *((const uint2*)(hin + (size_t)p2.x * CDIM) + lane16);
        uint2 q3 = *((const uint2*)(hin + (size_t)p3.x * CDIM) + lane16);
        float4 h0 = h4_to_f4(q0), h1 = h4_to_f4(q1);
        float4 h2 = h4_to_f4(q2), h3 = h4_to_f4(q3);
        float v0 = __int_as_float(p0.y), v1 = __int_as_float(p1.y);
        float v2 = __int_as_float(p2.y), v3 = __int_as_float(p3.y);
        acc.x += v0 * h0.x + v1 * h1.x + v2 * h2.x + v3 * h3.x;
        acc.y += v0 * h0.y + v1 * h1.y + v2 * h2.y + v3 * h3.y;
        acc.z += v0 * h0.z + v1 * h1.z + v2 * h2.z + v3 * h3.z;
        acc.w += v0 * h0.w + v1 * h1.w + v2 * h2.w + v3 * h3.w;
    }
    for (; i < e; i++) {
        int2 p0 = __ldg(&g_csr[i]);
        float v0 = __int_as_float(p0.y);
        float4 h0 = h4_to_f4(*((const uint2*)(hin + (size_t)p0.x * CDIM) + lane16));
        acc.x += v0 * h0.x; acc.y += v0 * h0.y;
        acc.z += v0 * h0.z; acc.w += v0 * h0.w;
    }
    return acc;
}

// spmm hop: fp16 gather in, fp32 + fp16 out. 2 rows per warp.
__global__ void spmm_h16(const __half* __restrict__ hin,
                         float* __restrict__ out32,
                         __half* __restrict__ out16, int n)
{
    int w = (blockIdx.x * blockDim.x + threadIdx.x) >> 5;
    int lane = threadIdx.x & 31;
    int r = w * 2 + (lane >> 4);
    if (r >= n) return;
    int lane16 = lane & 15;
    float4 acc = row_acc_h16(hin, g_off[r], g_off[r + 1], lane16);
    *((float4*)(out32 + (size_t)r * CDIM) + lane16) = acc;
    store_h4(out16 + (size_t)r * CDIM + lane16 * 4, acc);
}

// ---------------------------------------------------------------------------
// Mega-tail: hop-3 gather (fp16 T2) + poly (smem) + xproj + score + softmax
// + res + 3-layer MLP head.
// ---------------------------------------------------------------------------
#define TAIL_SMEM_FLOATS (64*68 + 64*68 + 64*137 + 128 + 64 + 64)

__global__ void mega_tail(const float* __restrict__ h,
                          const float* __restrict__ t1,
                          const float* __restrict__ t2,
                          const __half* __restrict__ t216,
                          const float* __restrict__ Wx,
                          const float* __restrict__ bWx,
                          const float* __restrict__ Wb,
                          const float* __restrict__ bWb,
                          const float* __restrict__ vc,
                          const float* __restrict__ W1,
                          const float* __restrict__ b1,
                          const float* __restrict__ W2,
                          const float* __restrict__ b2,
                          const float* __restrict__ W3,
                          const float* __restrict__ b3,
                          float* __restrict__ out, int nn)
{
    extern __shared__ float sm[];
    float* As  = sm;                 // [k][m] 64x68
    float* Ws  = As + 64 * 68;       // [k][n] 64x68
    float* Ps  = Ws + 64 * 68;       // [c][row] 64x137 (poly, 128 rows)
    float* Ss  = Ps + 64 * 137;      // 128 scores
    float* Sa0 = Ss + 128;
    float* Sa1 = Sa0 + 64;

    const int tid = threadIdx.x;
    const int b0 = blockIdx.x * 64;
    const int tx = tid & 15;
    const int ty = tid >> 4;

    // ---- loaders: h rows -> As (transposed), Wx -> Ws ----
    #pragma unroll
    for (int r = 0; r < 4; r++) {
        int i = tid + r * 256;
        int m = i >> 4, q = i & 15;
        int gn = b0 + m;
        float4 v = make_float4(0.f, 0.f, 0.f, 0.f);
        if (gn < nn) v = *((const float4*)(h + (size_t)gn * 64) + q);
        As[(q * 4 + 0) * 68 + m] = v.x;
        As[(q * 4 + 1) * 68 + m] = v.y;
        As[(q * 4 + 2) * 68 + m] = v.z;
        As[(q * 4 + 3) * 68 + m] = v.w;
    }
    #pragma unroll
    for (int r = 0; r < 4; r++) {
        int i = tid + r * 256;
        int k = i >> 4, nq = (i & 15) * 4;
        float4 v = *(const float4*)(Wx + (size_t)k * 64 + nq);
        Ws[k * 68 + nq]     = v.x; Ws[k * 68 + nq + 1] = v.y;
        Ws[k * 68 + nq + 2] = v.z; Ws[k * 68 + nq + 3] = v.w;
    }

    // ---- stage A: hop-3 gather + poly for this block's nodes -> Ps ----
    {
        int wid = tid >> 5;
        int lane = tid & 31;
        int lane16 = lane & 15;
        float c00 = g_coef[0], c01 = g_coef[1], c02 = g_coef[2], c03 = g_coef[3];
        float c10 = g_coef[4], c11 = g_coef[5], c12 = g_coef[6], c13 = g_coef[7];
        #pragma unroll
        for (int it = 0; it < 4; it++) {
            int local = wid * 8 + it * 2 + (lane >> 4);
            int r = b0 + local;
            float4 p0 = make_float4(0.f, 0.f, 0.f, 0.f);
            float4 p1 = make_float4(0.f, 0.f, 0.f, 0.f);
            if (r < nn) {
                float4 d = row_acc_h16(t216, g_off[r], g_off[r + 1], lane16);
                float4 a = *((const float4*)(h  + (size_t)r * CDIM) + lane16);
                float4 b = *((const float4*)(t1 + (size_t)r * CDIM) + lane16);
                float4 c = *((const float4*)(t2 + (size_t)r * CDIM) + lane16);
                p0.x = c00*a.x + c01*b.x + c02*c.x + c03*d.x;
                p0.y = c00*a.y + c01*b.y + c02*c.y + c03*d.y;
                p0.z = c00*a.z + c01*b.z + c02*c.z + c03*d.z;
                p0.w = c00*a.w + c01*b.w + c02*c.w + c03*d.w;
                p1.x = c10*a.x + c11*b.x + c12*c.x + c13*d.x;
                p1.y = c10*a.y + c11*b.y + c12*c.y + c13*d.y;
                p1.z = c10*a.z + c11*b.z + c12*c.z + c13*d.z;
                p1.w = c10*a.w + c11*b.w + c12*c.w + c13*d.w;
            }
            int cb = lane16 * 4;
            int m2 = 2 * local;
            Ps[(cb + 0) * 137 + m2] = p0.x; Ps[(cb + 0) * 137 + m2 + 1] = p1.x;
            Ps[(cb + 1) * 137 + m2] = p0.y; Ps[(cb + 1) * 137 + m2 + 1] = p1.y;
            Ps[(cb + 2) * 137 + m2] = p0.z; Ps[(cb + 2) * 137 + m2 + 1] = p1.z;
            Ps[(cb + 3) * 137 + m2] = p0.w; Ps[(cb + 3) * 137 + m2 + 1] = p1.w;
        }
    }
    __syncthreads();

    // ---- stage 1: xp = h @ Wx + bWx (register 4x4) ----
    float xp[4][4] = {};
    #pragma unroll
    for (int kk = 0; kk < 64; kk++) {
        float4 a = *(const float4*)&As[kk * 68 + ty * 4];
        float4 b = *(const float4*)&Ws[kk * 68 + tx * 4];
        float am[4] = {a.x, a.y, a.z, a.w};
        float bn[4] = {b.x, b.y, b.z, b.w};
        #pragma unroll
        for (int i = 0; i < 4; i++)
            #pragma unroll
            for (int j = 0; j < 4; j++)
                xp[i][j] += am[i] * bn[j];
    }
    {
        float4 bx = *(const float4*)(bWx + tx * 4);
        #pragma unroll
        for (int i = 0; i < 4; i++) {
            xp[i][0] += bx.x; xp[i][1] += bx.y;
            xp[i][2] += bx.z; xp[i][3] += bx.w;
        }
    }
    __syncthreads();

    // load Wb -> Ws
    #pragma unroll
    for (int r = 0; r < 4; r++) {
        int i = tid + r * 256;
        int k = i >> 4, nq = (i & 15) * 4;
        float4 v = *(const float4*)(Wb + (size_t)k * 64 + nq);
        Ws[k * 68 + nq]     = v.x; Ws[k * 68 + nq + 1] = v.y;
        Ws[k * 68 + nq + 2] = v.z; Ws[k * 68 + nq + 3] = v.w;
    }
    __syncthreads();

    // ---- stage 2: scores ----
    {
        float acc2[8][4] = {};
        #pragma unroll
        for (int kk = 0; kk < 64; kk++) {
            float4 b = *(const float4*)&Ws[kk * 68 + tx * 4];
            float bn[4] = {b.x, b.y, b.z, b.w};
            const float* pr = &Ps[kk * 137 + ty * 8];
            #pragma unroll
            for (int i = 0; i < 8; i++) {
                float av = pr[i];
                acc2[i][0] += av * bn[0];
                acc2[i][1] += av * bn[1];
                acc2[i][2] += av * bn[2];
                acc2[i][3] += av * bn[3];
            }
        }
        float4 bb = *(const float4*)(bWb + tx * 4);
        float4 vv = *(const float4*)(vc + tx * 4);
        #pragma unroll
        for (int i = 0; i < 8; i++) {
            int h2 = i >> 1;
            float part;
            part  = tanhf(acc2[i][0] + bb.x + xp[h2][0]) * vv.x;
            part += tanhf(acc2[i][1] + bb.y + xp[h2][1]) * vv.y;
            part += tanhf(acc2[i][2] + bb.z + xp[h2][2]) * vv.z;
            part += tanhf(acc2[i][3] + bb.w + xp[h2][3]) * vv.w;
            #pragma unroll
            for (int o = 8; o > 0; o >>= 1)
                part += __shfl_xor_sync(0xffffffffu, part, o);
            if (tx == 0) Ss[ty * 8 + i] = part;
        }
    }
    __syncthreads();

    // ---- softmax per node ----
    if (tid < 64) {
        float s0 = Ss[2 * tid], s1 = Ss[2 * tid + 1];
        float m = fmaxf(s0, s1);
        float e0 = expf(s0 - m), e1 = expf(s1 - m);
        float inv = 1.f / (e0 + e1);
        Sa0[tid] = e0 * inv;
        Sa1[tid] = e1 * inv;
    }
    __syncthreads();

    // ---- stage 3: res -> As, W1 -> Ws ----
    #pragma unroll
    for (int r = 0; r < 16; r++) {
        int i = tid + r * 256;
        int c = i >> 6, m = i & 63;
        As[c * 68 + m] = Sa0[m] * Ps[c * 137 + 2 * m]
                       + Sa1[m] * Ps[c * 137 + 2 * m + 1];
    }
    #pragma unroll
    for (int r = 0; r < 4; r++) {
        int i = tid + r * 256;
        int k = i >> 4, nq = (i & 15) * 4;
        float4 v = *(const float4*)(W1 + (size_t)k * 64 + nq);
        Ws[k * 68 + nq]     = v.x; Ws[k * 68 + nq + 1] = v.y;
        Ws[k * 68 + nq + 2] = v.z; Ws[k * 68 + nq + 3] = v.w;
    }
    __syncthreads();

    // ---- stage 4: y1 = relu(res @ W1 + b1) ----
    float acc[4][4] = {};
    #pragma unroll
    for (int kk = 0; kk < 64; kk++) {
        float4 a = *(const float4*)&As[kk * 68 + ty * 4];
        float4 b = *(const float4*)&Ws[kk * 68 + tx * 4];
        float am[4] = {a.x, a.y, a.z, a.w};
        float bn[4] = {b.x, b.y, b.z, b.w};
        #pragma unroll
        for (int i = 0; i < 4; i++)
            #pragma unroll
            for (int j = 0; j < 4; j++)
                acc[i][j] += am[i] * bn[j];
    }
    __syncthreads();

    {
        float4 bv = *(const float4*)(b1 + tx * 4);
        float bbv[4] = {bv.x, bv.y, bv.z, bv.w};
        #pragma unroll
        for (int i = 0; i < 4; i++)
            #pragma unroll
            for (int j = 0; j < 4; j++)
                As[(tx * 4 + j) * 68 + ty * 4 + i] = fmaxf(acc[i][j] + bbv[j], 0.f);
    }
    #pragma unroll
    for (int r = 0; r < 2; r++) {
        int i = tid + r * 256;
        int k = i >> 3, nq = (i & 7) * 4;
        float4 v = *(const float4*)(W2 + (size_t)k * 32 + nq);
        Ws[k * 68 + nq]     = v.x; Ws[k * 68 + nq + 1] = v.y;
        Ws[k * 68 + nq + 2] = v.z; Ws[k * 68 + nq + 3] = v.w;
    }
    __syncthreads();

    // ---- stage 5: y2 = relu(y1@W2+b2); out = y2@W3+b3 ----
    const int tx2 = tid & 15;
    const int ty2 = tid >> 4;
    float acc3[4][2] = {};
    #pragma unroll
    for (int kk = 0; kk < 64; kk++) {
        float4 a = *(const float4*)&As[kk * 68 + ty2 * 4];
        float b0v = Ws[kk * 68 + tx2 * 2];
        float b1v = Ws[kk * 68 + tx2 * 2 + 1];
        float am[4] = {a.x, a.y, a.z, a.w};
        #pragma unroll
        for (int i = 0; i < 4; i++) {
            acc3[i][0] += am[i] * b0v;
            acc3[i][1] += am[i] * b1v;
        }
    }
    float bb0 = b2[tx2 * 2], bb1 = b2[tx2 * 2 + 1];
    float w00 = W3[(tx2 * 2) * 2],     w01 = W3[(tx2 * 2) * 2 + 1];
    float w10 = W3[(tx2 * 2 + 1) * 2], w11 = W3[(tx2 * 2 + 1) * 2 + 1];

    #pragma unroll
    for (int i = 0; i < 4; i++) {
        float y0 = fmaxf(acc3[i][0] + bb0, 0.f);
        float y1v = fmaxf(acc3[i][1] + bb1, 0.f);
        float s0 = y0 * w00 + y1v * w10;
        float s1 = y0 * w01 + y1v * w11;
        #pragma unroll
        for (int o = 8; o > 0; o >>= 1) {
            s0 += __shfl_xor_sync(0xffffffffu, s0, o);
            s1 += __shfl_xor_sync(0xffffffffu, s1, o);
        }
        int gm = b0 + ty2 * 4 + i;
        if (tx2 == 0 && gm < nn) {
            out[gm * 2]     = s0 + b3[0];
            out[gm * 2 + 1] = s1 + b3[1];
        }
    }
}

// ---------------------------------------------------------------------------
extern "C" void kernel_launch(void* const* d_in, const int* in_sizes, int n_in,
                              void* d_out, int out_size)
{
    const float* x      = (const float*)d_in[0];
    const void*  esrc   = d_in[1];
    const void*  edst   = d_in[2];
    const float* ev     = (const float*)d_in[3];
    const float* Win    = (const float*)d_in[4];
    const float* bin    = (const float*)d_in[5];
    const float* thetas = (const float*)d_in[6];
    const float* Wb     = (const float*)d_in[7];
    const float* bWb    = (const float*)d_in[8];
    const float* Wx     = (const float*)d_in[9];
    const float* bWx    = (const float*)d_in[10];
    const float* vc     = (const float*)d_in[11];
    const float* W1     = (const float*)d_in[12];
    const float* b1     = (const float*)d_in[13];
    const float* W2     = (const float*)d_in[14];
    const float* b2     = (const float*)d_in[15];
    const float* W3     = (const float*)d_in[16];
    const float* b3     = (const float*)d_in[17];

    int n = in_sizes[0] / 128;
    int E = in_sizes[3];

    float *ph, *pT1, *pT2;
    __half *ph16, *pT116, *pT216;
    cudaGetSymbolAddress((void**)&ph,    g_h);
    cudaGetSymbolAddress((void**)&pT1,   g_T1);
    cudaGetSymbolAddress((void**)&pT2,   g_T2);
    cudaGetSymbolAddress((void**)&ph16,  g_h16);
    cudaGetSymbolAddress((void**)&pT116, g_T116);
    cudaGetSymbolAddress((void**)&pT216, g_T216);

    static int smem_set = 0;
    const int tail_smem = TAIL_SMEM_FLOATS * (int)sizeof(float);
    if (!smem_set) {
        cudaFuncSetAttribute(mega_tail,
                             cudaFuncAttributeMaxDynamicSharedMemorySize,
                             tail_smem);
        smem_set = 1;
    }

    prep_kernel<<<1, 32>>>(esrc, thetas);

    int GBt = (n + 127) / 128;          // total gemm blocks
    int GA  = GBt / 2;                  // fat1 gemm blocks
    int GB  = GBt - GA;                 // fat2 gemm blocks
    int CB  = (E + 255) / 256;          // count/scatter blocks
    int OB  = (n + 255) / 256;          // off-writer blocks
    int nb  = (n + 1023) / 1024;

    // fat1: gemm rows [0, GA*128) || count histogram
    fat1<<<GA + CB, 256>>>(x, Win, bin, ph, ph16, n, edst, E, GA);

    scan1_kernel<<<nb, 1024>>>(n);
    scan2_kernel<<<1, 128>>>(nb);

    // fat2: gemm rows [GA*128, n) || off-writer || scatter
    fat2<<<GB + OB + CB, 256>>>(x, Win, bin, ph, ph16, n,
                                esrc, edst, ev, E, n, GA, GB, OB);

    // hops 1, 2 (fp16 gathers, fp32 accumulate)
    int warps = (n + 1) / 2;
    int sb = (warps * 32 + 255) / 256;
    spmm_h16<<<sb, 256>>>(ph16,  pT1, pT116, n);
    spmm_h16<<<sb, 256>>>(pT116, pT2, pT216, n);

    // fused hop-3 + poly + attention + MLP
    mega_tail<<<(n + 63) / 64, 256, tail_smem>>>(
        ph, pT1, pT2, pT216, Wx, bWx, Wb, bWb, vc,
        W1, b1, W2, b2, W3, b3, (float*)d_out, n);
}